// round 3
// baseline (speedup 1.0000x reference)
#include <cuda_runtime.h>
#include <math.h>

#define HH 512
#define WW 512
#define BB 32
#define CCH 3
#define NF 8
#define NK 6
#define TWO_PI 6.283185307179586f

// Scratch (device globals — no allocation allowed)
__device__ float g_G[BB * CCH * NK * WW * 2];    // [bc][k][w][re,im] column-DFT result
__device__ float g_gg[BB * CCH * HH * NK * 2];   // [bc][h][k][re,im] row-contracted coeffs

// ---------------------------------------------------------------------------
// Kernel 1: column DFT. For each (b,c,w): G[k] = sum_h x[h,w] * e^{-2pi i (k-3) h / 512}
// grid: (W/256, B*C), block 256. Coalesced reads of x, one full pass over input.
// ---------------------------------------------------------------------------
__global__ __launch_bounds__(256) void k1_coldft(const float* __restrict__ x) {
    const int bc = blockIdx.y;
    const int w  = blockIdx.x * 256 + threadIdx.x;

    __shared__ float4 tw[HH][3];   // twiddles: per h, 6 (cos,sin) pairs packed in 3 float4
    for (int h = threadIdx.x; h < HH; h += 256) {
        float base = -TWO_PI * (float)h / (float)HH;
        float c[6], s[6];
#pragma unroll
        for (int k = 0; k < 6; k++) {
            float a = base * (float)(k - 3);
            sincosf(a, &s[k], &c[k]);
        }
        tw[h][0] = make_float4(c[0], s[0], c[1], s[1]);
        tw[h][1] = make_float4(c[2], s[2], c[3], s[3]);
        tw[h][2] = make_float4(c[4], s[4], c[5], s[5]);
    }
    __syncthreads();

    float ar[6] = {0.f,0.f,0.f,0.f,0.f,0.f};
    float ai[6] = {0.f,0.f,0.f,0.f,0.f,0.f};
    const float* xp = x + (size_t)bc * HH * WW + w;

#pragma unroll 4
    for (int h = 0; h < HH; ++h) {
        float v = __ldg(xp + (size_t)h * WW);
        float4 t0 = tw[h][0], t1 = tw[h][1], t2 = tw[h][2];
        ar[0] = fmaf(v, t0.x, ar[0]); ai[0] = fmaf(v, t0.y, ai[0]);
        ar[1] = fmaf(v, t0.z, ar[1]); ai[1] = fmaf(v, t0.w, ai[1]);
        ar[2] = fmaf(v, t1.x, ar[2]); ai[2] = fmaf(v, t1.y, ai[2]);
        ar[3] = fmaf(v, t1.z, ar[3]); ai[3] = fmaf(v, t1.w, ai[3]);
        ar[4] = fmaf(v, t2.x, ar[4]); ai[4] = fmaf(v, t2.y, ai[4]);
        ar[5] = fmaf(v, t2.z, ar[5]); ai[5] = fmaf(v, t2.w, ai[5]);
    }

    float* gp = g_G + (size_t)bc * NK * WW * 2;
#pragma unroll
    for (int k = 0; k < 6; k++) {
        gp[((size_t)k * WW + w) * 2 + 0] = ar[k];
        gp[((size_t)k * WW + w) * 2 + 1] = ai[k];
    }
}

// ---------------------------------------------------------------------------
// Kernel 2: per (b,c): F[u][v] = sum_w G[u][w] e^{-2pi i (v-3) w/512}, normalized
// by 1/(H*W). Then g_gg[h][k] = sum_u F[u][k] e^{+2pi i (u-3) h/512}.
// grid: 96 blocks, 512 threads.
// ---------------------------------------------------------------------------
__global__ __launch_bounds__(512) void k2_reduce() {
    const int bc = blockIdx.x;
    const int t  = threadIdx.x;           // phase A: t = w ; phase B: t = h
    const int wid = t >> 5, lid = t & 31;

    __shared__ float part[16][72];
    __shared__ float F[72];               // [u][k][re,im]

    // ---- phase A: reduce over w ----
    {
        float phi = TWO_PI * (float)t / (float)WW;
        float c1, s1; sincosf(phi, &s1, &c1);
        float c2 = c1 * c1 - s1 * s1, s2 = 2.f * c1 * s1;
        float c3 = c2 * c1 - s2 * s1, s3 = c2 * s1 + s2 * c1;
        // E[k] = e^{-i (k-3) phi}
        float Ec[6] = { c3, c2, c1, 1.f, c1,  c2 };
        float Es[6] = { s3, s2, s1, 0.f, -s1, -s2 };

        const float* gp = g_G + (size_t)bc * NK * WW * 2;
#pragma unroll
        for (int u = 0; u < 6; u++) {
            float gr = gp[((size_t)u * WW + t) * 2 + 0];
            float gi = gp[((size_t)u * WW + t) * 2 + 1];
            float pr[6], pi[6];
#pragma unroll
            for (int k = 0; k < 6; k++) {
                pr[k] = gr * Ec[k] - gi * Es[k];
                pi[k] = gr * Es[k] + gi * Ec[k];
            }
            // warp butterfly reduce
#pragma unroll
            for (int off = 16; off >= 1; off >>= 1) {
#pragma unroll
                for (int k = 0; k < 6; k++) {
                    pr[k] += __shfl_xor_sync(0xFFFFFFFFu, pr[k], off);
                    pi[k] += __shfl_xor_sync(0xFFFFFFFFu, pi[k], off);
                }
            }
            if (lid == 0) {
#pragma unroll
                for (int k = 0; k < 6; k++) {
                    part[wid][(u * 6 + k) * 2 + 0] = pr[k];
                    part[wid][(u * 6 + k) * 2 + 1] = pi[k];
                }
            }
        }
    }
    __syncthreads();
    if (t < 72) {
        float s = 0.f;
#pragma unroll
        for (int q = 0; q < 16; q++) s += part[q][t];
        F[t] = s * (1.0f / ((float)HH * (float)WW));
    }
    __syncthreads();

    // ---- phase B: t = h, compute gg[h][k] ----
    {
        float psi = TWO_PI * (float)t / (float)HH;
        float d1c, d1s; sincosf(psi, &d1s, &d1c);
        float d2c = d1c * d1c - d1s * d1s, d2s = 2.f * d1c * d1s;
        float d3c = d2c * d1c - d2s * d1s, d3s = d2c * d1s + d2s * d1c;
        // D[u] = e^{+i (u-3) psi}
        float Dc[6] = { d3c,  d2c,  d1c,  1.f, d1c, d2c };
        float Ds[6] = { -d3s, -d2s, -d1s, 0.f, d1s, d2s };

        float* ggp = g_gg + (((size_t)bc * HH + t) * NK) * 2;
#pragma unroll
        for (int k = 0; k < 6; k++) {
            float gr = 0.f, gi = 0.f;
#pragma unroll
            for (int u = 0; u < 6; u++) {
                float Fr = F[(u * 6 + k) * 2 + 0];
                float Fi = F[(u * 6 + k) * 2 + 1];
                gr += Fr * Dc[u] - Fi * Ds[u];
                gi += Fr * Ds[u] + Fi * Dc[u];
            }
            ggp[k * 2 + 0] = gr;
            ggp[k * 2 + 1] = gi;
        }
    }
}

// ---------------------------------------------------------------------------
// Kernel 3: reconstruction + MLP + residual + clip.
// lp[c] = | sum_k gg[c][h][k] * e^{i k phi_w} |  (Horner; e^{-3i phi} phase drops)
// grid: (H/4, B), block 512 (thread = w), 4 rows per block.
// Per-row payload in shared: 3 ch * 6 k * 2 = 36 floats; 4 rows = 144 floats.
// ---------------------------------------------------------------------------
__global__ __launch_bounds__(512) void k3_final(const float* __restrict__ w1,
                                                const float* __restrict__ b1,
                                                const float* __restrict__ w2,
                                                const float* __restrict__ b2,
                                                float* __restrict__ out) {
    const int b  = blockIdx.y;
    const int h0 = blockIdx.x * 4;
    const int t  = threadIdx.x;   // w

    __shared__ __align__(16) float sg[144];   // [r][ch][k][re,im] : 4*3*6*2
    __shared__ float wt[64];                  // w1(24) b1(8) w2(24) b2(3)

    if (t < 144) {
        int r  = t / 36;
        int ch = (t % 36) / 12;
        int j  = t % 12;
        sg[t] = g_gg[(((size_t)(b * 3 + ch) * HH) + (h0 + r)) * 12 + j];
    } else if (t >= 256 && t < 256 + 24) {
        wt[t - 256] = w1[t - 256];
    } else if (t >= 256 + 24 && t < 256 + 32) {
        wt[t - 256] = b1[t - 280];
    } else if (t >= 256 + 32 && t < 256 + 56) {
        wt[t - 256] = w2[t - 288];
    } else if (t >= 256 + 56 && t < 256 + 59) {
        wt[t - 256] = b2[t - 312];
    }
    __syncthreads();

    // weights to registers
    float W1r[8][3], B1r[8], W2r[3][8], B2r[3];
#pragma unroll
    for (int j = 0; j < 8; j++) {
#pragma unroll
        for (int cc = 0; cc < 3; cc++) W1r[j][cc] = wt[j * 3 + cc];
        B1r[j] = wt[24 + j];
    }
#pragma unroll
    for (int cc = 0; cc < 3; cc++) {
#pragma unroll
        for (int j = 0; j < 8; j++) W2r[cc][j] = wt[32 + cc * 8 + j];
        B2r[cc] = wt[56 + cc];
    }

    float phi = TWO_PI * (float)t / (float)WW;
    float cr, ci; sincosf(phi, &ci, &cr);     // c = e^{i phi}

#pragma unroll
    for (int r = 0; r < 4; r++) {
        float lp[3];
#pragma unroll
        for (int ch = 0; ch < 3; ch++) {
            const float2* g = (const float2*)&sg[(r * 3 + ch) * 12];
            float arr = g[5].x, aii = g[5].y;
#pragma unroll
            for (int k = 4; k >= 0; --k) {
                float2 gk = g[k];
                float nr = fmaf(arr, cr, fmaf(-aii, ci, gk.x));
                float ni = fmaf(arr, ci, fmaf(aii, cr, gk.y));
                arr = nr; aii = ni;
            }
            lp[ch] = sqrtf(fmaf(arr, arr, aii * aii));
        }

        float hv[8];
#pragma unroll
        for (int j = 0; j < 8; j++) {
            float a = B1r[j];
            a = fmaf(W1r[j][0], lp[0], a);
            a = fmaf(W1r[j][1], lp[1], a);
            a = fmaf(W1r[j][2], lp[2], a);
            hv[j] = fmaxf(a, 0.f);
        }
#pragma unroll
        for (int ch = 0; ch < 3; ch++) {
            float y = B2r[ch] + lp[ch];
#pragma unroll
            for (int j = 0; j < 8; j++) y = fmaf(W2r[ch][j], hv[j], y);
            y = fminf(fmaxf(y, 0.f), 1.f);
            out[(((size_t)(b * 3 + ch) * HH) + (h0 + r)) * WW + t] = y;
        }
    }
}

// ---------------------------------------------------------------------------
extern "C" void kernel_launch(void* const* d_in, const int* in_sizes, int n_in,
                              void* d_out, int out_size) {
    const float* x  = (const float*)d_in[0];
    const float* w1 = (const float*)d_in[1];
    const float* b1 = (const float*)d_in[2];
    const float* w2 = (const float*)d_in[3];
    const float* b2 = (const float*)d_in[4];
    float* out = (float*)d_out;

    k1_coldft<<<dim3(WW / 256, BB * CCH), 256>>>(x);
    k2_reduce<<<BB * CCH, 512>>>();
    k3_final<<<dim3(HH / 4, BB), 512>>>(w1, b1, w2, b2, out);
}

// round 4
// speedup vs baseline: 1.4475x; 1.4475x over previous
#include <cuda_runtime.h>
#include <math.h>

#define HH 512
#define WW 512
#define BB 32
#define CCH 3
#define NK 6
#define NCHUNK 16
#define CROWS 32          // HH / NCHUNK
#define TWO_PI 6.283185307179586f

// Scratch (device globals — no allocation allowed)
__device__ float g_Fpart[BB * CCH * NCHUNK * 72];  // [bc][chunk][u*6+k][re,im]
__device__ float g_gg[BB * CCH * HH * NK * 2];     // [bc][h][k][re,im]

// ---------------------------------------------------------------------------
// Kernel 1: per (chunk,bc) block computes partial F[u][k] = sum over its
// 32-row x 512-col tile of x[h,w] * e^{-2pi i (u-3) h/512} * e^{-2pi i (k-3) w/512}
// Block 128 threads, thread = float4 of w. Grid (16, 96) = 1536 blocks.
// ---------------------------------------------------------------------------
__global__ __launch_bounds__(128) void k1_coldft(const float* __restrict__ x) {
    const int chunk = blockIdx.x;
    const int bc    = blockIdx.y;
    const int t     = threadIdx.x;
    const int h0    = chunk * CROWS;

    __shared__ float twc[CROWS][6], tws[CROWS][6];
    __shared__ float sm_part[4][72];

    for (int i = t; i < CROWS * 6; i += 128) {
        int hl = i / 6, k = i % 6;
        float a = -TWO_PI * (float)(h0 + hl) * (1.0f / (float)HH) * (float)(k - 3);
        float s, c; __sincosf(a, &s, &c);
        twc[hl][k] = c; tws[hl][k] = s;
    }
    __syncthreads();

    // column sums over this chunk's rows: col[u][j] complex, j = lane's 4 w's
    float cre[6][4], cim[6][4];
#pragma unroll
    for (int u = 0; u < 6; u++)
#pragma unroll
        for (int j = 0; j < 4; j++) { cre[u][j] = 0.f; cim[u][j] = 0.f; }

    const float4* xp = (const float4*)(x + (size_t)bc * HH * WW + (size_t)h0 * WW) + t;
#pragma unroll 4
    for (int hl = 0; hl < CROWS; ++hl) {
        float4 v = __ldg(xp + (size_t)hl * (WW / 4));
#pragma unroll
        for (int u = 0; u < 6; u++) {
            float c = twc[hl][u], s = tws[hl][u];
            cre[u][0] = fmaf(v.x, c, cre[u][0]); cim[u][0] = fmaf(v.x, s, cim[u][0]);
            cre[u][1] = fmaf(v.y, c, cre[u][1]); cim[u][1] = fmaf(v.y, s, cim[u][1]);
            cre[u][2] = fmaf(v.z, c, cre[u][2]); cim[u][2] = fmaf(v.z, s, cim[u][2]);
            cre[u][3] = fmaf(v.w, c, cre[u][3]); cim[u][3] = fmaf(v.w, s, cim[u][3]);
        }
    }

    // E_k[w] for this thread's 4 w's: e^{-i (k-3) phi_w}, k-3 in {-3..2}
    float Ec[4][6], Es[4][6];
#pragma unroll
    for (int j = 0; j < 4; j++) {
        float phi = TWO_PI * (float)(4 * t + j) * (1.0f / (float)WW);
        float c1, s1; __sincosf(phi, &s1, &c1);
        float c2 = c1 * c1 - s1 * s1, s2 = 2.f * c1 * s1;
        float c3 = c2 * c1 - s2 * s1, s3 = c2 * s1 + s2 * c1;
        Ec[j][0] = c3; Es[j][0] = s3;
        Ec[j][1] = c2; Es[j][1] = s2;
        Ec[j][2] = c1; Es[j][2] = s1;
        Ec[j][3] = 1.f; Es[j][3] = 0.f;
        Ec[j][4] = c1; Es[j][4] = -s1;
        Ec[j][5] = c2; Es[j][5] = -s2;
    }

    const int wid = t >> 5, lid = t & 31;
    // process u one at a time to bound register pressure; warp-reduce 12 floats
#pragma unroll
    for (int u = 0; u < 6; u++) {
        float fr[6], fi[6];
#pragma unroll
        for (int k = 0; k < 6; k++) { fr[k] = 0.f; fi[k] = 0.f; }
#pragma unroll
        for (int j = 0; j < 4; j++) {
            float gr = cre[u][j], gi = cim[u][j];
#pragma unroll
            for (int k = 0; k < 6; k++) {
                fr[k] = fmaf(gr, Ec[j][k], fmaf(-gi, Es[j][k], fr[k]));
                fi[k] = fmaf(gr, Es[j][k], fmaf( gi, Ec[j][k], fi[k]));
            }
        }
#pragma unroll
        for (int off = 16; off >= 1; off >>= 1) {
#pragma unroll
            for (int k = 0; k < 6; k++) {
                fr[k] += __shfl_xor_sync(0xFFFFFFFFu, fr[k], off);
                fi[k] += __shfl_xor_sync(0xFFFFFFFFu, fi[k], off);
            }
        }
        if (lid == 0) {
#pragma unroll
            for (int k = 0; k < 6; k++) {
                sm_part[wid][(u * 6 + k) * 2 + 0] = fr[k];
                sm_part[wid][(u * 6 + k) * 2 + 1] = fi[k];
            }
        }
    }
    __syncthreads();

    if (t < 72) {
        float s = sm_part[0][t] + sm_part[1][t] + sm_part[2][t] + sm_part[3][t];
        g_Fpart[((size_t)bc * NCHUNK + chunk) * 72 + t] = s;
    }
}

// ---------------------------------------------------------------------------
// Kernel 2: per (b,c): sum chunk partials -> F (normalized), then
// g_gg[h][k] = sum_u F[u][k] e^{+2pi i (u-3) h/512}.  grid 96, block 512.
// ---------------------------------------------------------------------------
__global__ __launch_bounds__(512) void k2_reduce() {
    const int bc = blockIdx.x;
    const int t  = threadIdx.x;

    __shared__ float F[72];   // [u*6+k][re,im]

    if (t < 72) {
        const float* fp = g_Fpart + (size_t)bc * NCHUNK * 72 + t;
        float s = 0.f;
#pragma unroll
        for (int c = 0; c < NCHUNK; c++) s += fp[c * 72];
        F[t] = s * (1.0f / ((float)HH * (float)WW));
    }
    __syncthreads();

    // t = h
    {
        float psi = TWO_PI * (float)t * (1.0f / (float)HH);
        float d1c, d1s; __sincosf(psi, &d1s, &d1c);
        float d2c = d1c * d1c - d1s * d1s, d2s = 2.f * d1c * d1s;
        float d3c = d2c * d1c - d2s * d1s, d3s = d2c * d1s + d2s * d1c;
        // D[u] = e^{+i (u-3) psi}
        float Dc[6] = { d3c,  d2c,  d1c,  1.f, d1c, d2c };
        float Ds[6] = { -d3s, -d2s, -d1s, 0.f, d1s, d2s };

        float* ggp = g_gg + (((size_t)bc * HH + t) * NK) * 2;
#pragma unroll
        for (int k = 0; k < 6; k++) {
            float gr = 0.f, gi = 0.f;
#pragma unroll
            for (int u = 0; u < 6; u++) {
                float Fr = F[(u * 6 + k) * 2 + 0];
                float Fi = F[(u * 6 + k) * 2 + 1];
                gr += Fr * Dc[u] - Fi * Ds[u];
                gi += Fr * Ds[u] + Fi * Dc[u];
            }
            ggp[k * 2 + 0] = gr;
            ggp[k * 2 + 1] = gi;
        }
    }
}

// ---------------------------------------------------------------------------
// Kernel 3: reconstruction + MLP + residual + clip.
// lp[c] = | sum_k gg[c][h][k] e^{i k phi_w} |  (e^{-3i phi} phase drops in |.|)
// grid (H/4, B), block 512 (thread = w), 4 rows per block.
// ---------------------------------------------------------------------------
__global__ __launch_bounds__(512) void k3_final(const float* __restrict__ w1,
                                                const float* __restrict__ b1,
                                                const float* __restrict__ w2,
                                                const float* __restrict__ b2,
                                                float* __restrict__ out) {
    const int b  = blockIdx.y;
    const int h0 = blockIdx.x * 4;
    const int t  = threadIdx.x;   // w

    __shared__ __align__(16) float sg[144];   // [r][ch][k][re,im] : 4*3*6*2
    __shared__ float wt[64];                  // w1(24) b1(8) w2(24) b2(3)

    if (t < 144) {
        int r  = t / 36;
        int ch = (t % 36) / 12;
        int j  = t % 12;
        sg[t] = g_gg[(((size_t)(b * 3 + ch) * HH) + (h0 + r)) * 12 + j];
    } else if (t >= 256 && t < 256 + 24) {
        wt[t - 256] = w1[t - 256];
    } else if (t >= 256 + 24 && t < 256 + 32) {
        wt[t - 256] = b1[t - 280];
    } else if (t >= 256 + 32 && t < 256 + 56) {
        wt[t - 256] = w2[t - 288];
    } else if (t >= 256 + 56 && t < 256 + 59) {
        wt[t - 256] = b2[t - 312];
    }
    __syncthreads();

    float W1r[8][3], B1r[8], W2r[3][8], B2r[3];
#pragma unroll
    for (int j = 0; j < 8; j++) {
#pragma unroll
        for (int cc = 0; cc < 3; cc++) W1r[j][cc] = wt[j * 3 + cc];
        B1r[j] = wt[24 + j];
    }
#pragma unroll
    for (int cc = 0; cc < 3; cc++) {
#pragma unroll
        for (int j = 0; j < 8; j++) W2r[cc][j] = wt[32 + cc * 8 + j];
        B2r[cc] = wt[56 + cc];
    }

    float phi = TWO_PI * (float)t * (1.0f / (float)WW);
    float cr, ci; __sincosf(phi, &ci, &cr);   // c = e^{i phi}

#pragma unroll
    for (int r = 0; r < 4; r++) {
        float lp[3];
#pragma unroll
        for (int ch = 0; ch < 3; ch++) {
            const float2* g = (const float2*)&sg[(r * 3 + ch) * 12];
            float arr = g[5].x, aii = g[5].y;
#pragma unroll
            for (int k = 4; k >= 0; --k) {
                float2 gk = g[k];
                float nr = fmaf(arr, cr, fmaf(-aii, ci, gk.x));
                float ni = fmaf(arr, ci, fmaf(aii, cr, gk.y));
                arr = nr; aii = ni;
            }
            lp[ch] = sqrtf(fmaf(arr, arr, aii * aii));
        }

        float hv[8];
#pragma unroll
        for (int j = 0; j < 8; j++) {
            float a = B1r[j];
            a = fmaf(W1r[j][0], lp[0], a);
            a = fmaf(W1r[j][1], lp[1], a);
            a = fmaf(W1r[j][2], lp[2], a);
            hv[j] = fmaxf(a, 0.f);
        }
#pragma unroll
        for (int ch = 0; ch < 3; ch++) {
            float y = B2r[ch] + lp[ch];
#pragma unroll
            for (int j = 0; j < 8; j++) y = fmaf(W2r[ch][j], hv[j], y);
            y = fminf(fmaxf(y, 0.f), 1.f);
            out[(((size_t)(b * 3 + ch) * HH) + (h0 + r)) * WW + t] = y;
        }
    }
}

// ---------------------------------------------------------------------------
extern "C" void kernel_launch(void* const* d_in, const int* in_sizes, int n_in,
                              void* d_out, int out_size) {
    const float* x  = (const float*)d_in[0];
    const float* w1 = (const float*)d_in[1];
    const float* b1 = (const float*)d_in[2];
    const float* w2 = (const float*)d_in[3];
    const float* b2 = (const float*)d_in[4];
    float* out = (float*)d_out;

    k1_coldft<<<dim3(NCHUNK, BB * CCH), 128>>>(x);
    k2_reduce<<<BB * CCH, 512>>>();
    k3_final<<<dim3(HH / 4, BB), 512>>>(w1, b1, w2, b2, out);
}

// round 5
// speedup vs baseline: 1.8159x; 1.2545x over previous
#include <cuda_runtime.h>
#include <math.h>

#define HH 512
#define WW 512
#define BB 32
#define CCH 3
#define NK 6
#define NCHUNK 8
#define CROWS 64          // HH / NCHUNK
#define R3ROWS 16
#define TWO_PI 6.283185307179586f

typedef unsigned long long u64;

__device__ __forceinline__ u64 pk(float lo, float hi) {
    u64 r; asm("mov.b64 %0,{%1,%2};" : "=l"(r) : "f"(lo), "f"(hi)); return r;
}
__device__ __forceinline__ float2 upk(u64 v) {
    float2 f; asm("mov.b64 {%0,%1},%2;" : "=f"(f.x), "=f"(f.y) : "l"(v)); return f;
}
__device__ __forceinline__ u64 fma2_(u64 a, u64 b, u64 c) {
    u64 d; asm("fma.rn.f32x2 %0,%1,%2,%3;" : "=l"(d) : "l"(a), "l"(b), "l"(c)); return d;
}
__device__ __forceinline__ u64 mul2_(u64 a, u64 b) {
    u64 d; asm("mul.rn.f32x2 %0,%1,%2;" : "=l"(d) : "l"(a), "l"(b)); return d;
}
__device__ __forceinline__ u64 neg2_(u64 a) { return a ^ 0x8000000080000000ULL; }

// Scratch (device globals — no allocation allowed)
__device__ float g_Fpart[BB * CCH * NCHUNK * 72];  // [bc][chunk][u*6+k][re,im]
__device__ float g_gg[BB * CCH * HH * NK * 2];     // [bc][h][k][re,im]

// ---------------------------------------------------------------------------
// Kernel 1: per (chunk,bc) block computes partial F[u][k] over a 64-row tile.
// Main loop packed with fma.rn.f32x2 (2 w's per 64-bit lane-pair).
// Block 128 threads, thread = float4 of w. Grid (8, 96) = 768 blocks.
// ---------------------------------------------------------------------------
__global__ __launch_bounds__(128) void k1_coldft(const float* __restrict__ x) {
    const int chunk = blockIdx.x;
    const int bc    = blockIdx.y;
    const int t     = threadIdx.x;
    const int h0    = chunk * CROWS;

    __shared__ float4 tw4[CROWS][6];   // (c, c, s, s) per (row, u)
    __shared__ float sm_part[4][72];

    for (int i = t; i < CROWS * 6; i += 128) {
        int hl = i / 6, k = i % 6;
        float a = -TWO_PI * (float)(h0 + hl) * (1.0f / (float)HH) * (float)(k - 3);
        float s, c; __sincosf(a, &s, &c);
        tw4[hl][k] = make_float4(c, c, s, s);
    }
    __syncthreads();

    u64 cre01[6], cim01[6], cre23[6], cim23[6];
#pragma unroll
    for (int u = 0; u < 6; u++) { cre01[u] = 0ULL; cim01[u] = 0ULL; cre23[u] = 0ULL; cim23[u] = 0ULL; }

    const float4* xp = (const float4*)(x + (size_t)bc * HH * WW + (size_t)h0 * WW) + t;
#pragma unroll 8
    for (int hl = 0; hl < CROWS; ++hl) {
        float4 v = __ldg(xp + (size_t)hl * (WW / 4));
        u64 v01 = pk(v.x, v.y), v23 = pk(v.z, v.w);
#pragma unroll
        for (int u = 0; u < 6; u++) {
            float4 f = tw4[hl][u];
            u64 cc = pk(f.x, f.y), ss = pk(f.z, f.w);
            cre01[u] = fma2_(v01, cc, cre01[u]);
            cim01[u] = fma2_(v01, ss, cim01[u]);
            cre23[u] = fma2_(v23, cc, cre23[u]);
            cim23[u] = fma2_(v23, ss, cim23[u]);
        }
    }

    // unpack column sums to scalars
    float cre[6][4], cim[6][4];
#pragma unroll
    for (int u = 0; u < 6; u++) {
        float2 a = upk(cre01[u]); cre[u][0] = a.x; cre[u][1] = a.y;
        float2 b = upk(cre23[u]); cre[u][2] = b.x; cre[u][3] = b.y;
        float2 c = upk(cim01[u]); cim[u][0] = c.x; cim[u][1] = c.y;
        float2 d = upk(cim23[u]); cim[u][2] = d.x; cim[u][3] = d.y;
    }

    // E_k[w] = e^{-i (k-3) phi_w} for this thread's 4 w's
    float Ec[4][6], Es[4][6];
#pragma unroll
    for (int j = 0; j < 4; j++) {
        float phi = TWO_PI * (float)(4 * t + j) * (1.0f / (float)WW);
        float c1, s1; __sincosf(phi, &s1, &c1);
        float c2 = c1 * c1 - s1 * s1, s2 = 2.f * c1 * s1;
        float c3 = c2 * c1 - s2 * s1, s3 = c2 * s1 + s2 * c1;
        Ec[j][0] = c3; Es[j][0] = s3;
        Ec[j][1] = c2; Es[j][1] = s2;
        Ec[j][2] = c1; Es[j][2] = s1;
        Ec[j][3] = 1.f; Es[j][3] = 0.f;
        Ec[j][4] = c1; Es[j][4] = -s1;
        Ec[j][5] = c2; Es[j][5] = -s2;
    }

    const int wid = t >> 5, lid = t & 31;
#pragma unroll
    for (int u = 0; u < 6; u++) {
        float fr[6], fi[6];
#pragma unroll
        for (int k = 0; k < 6; k++) { fr[k] = 0.f; fi[k] = 0.f; }
#pragma unroll
        for (int j = 0; j < 4; j++) {
            float gr = cre[u][j], gi = cim[u][j];
#pragma unroll
            for (int k = 0; k < 6; k++) {
                fr[k] = fmaf(gr, Ec[j][k], fmaf(-gi, Es[j][k], fr[k]));
                fi[k] = fmaf(gr, Es[j][k], fmaf( gi, Ec[j][k], fi[k]));
            }
        }
#pragma unroll
        for (int off = 16; off >= 1; off >>= 1) {
#pragma unroll
            for (int k = 0; k < 6; k++) {
                fr[k] += __shfl_xor_sync(0xFFFFFFFFu, fr[k], off);
                fi[k] += __shfl_xor_sync(0xFFFFFFFFu, fi[k], off);
            }
        }
        if (lid == 0) {
#pragma unroll
            for (int k = 0; k < 6; k++) {
                sm_part[wid][(u * 6 + k) * 2 + 0] = fr[k];
                sm_part[wid][(u * 6 + k) * 2 + 1] = fi[k];
            }
        }
    }
    __syncthreads();

    if (t < 72) {
        float s = sm_part[0][t] + sm_part[1][t] + sm_part[2][t] + sm_part[3][t];
        g_Fpart[((size_t)bc * NCHUNK + chunk) * 72 + t] = s;
    }
}

// ---------------------------------------------------------------------------
// Kernel 2: per (b,c): sum chunk partials -> F (normalized), then
// g_gg[h][k] = sum_u F[u][k] e^{+2pi i (u-3) h/512}.  grid 96, block 512.
// ---------------------------------------------------------------------------
__global__ __launch_bounds__(512) void k2_reduce() {
    const int bc = blockIdx.x;
    const int t  = threadIdx.x;

    __shared__ float F[72];

    if (t < 72) {
        const float* fp = g_Fpart + (size_t)bc * NCHUNK * 72 + t;
        float s = 0.f;
#pragma unroll
        for (int c = 0; c < NCHUNK; c++) s += fp[c * 72];
        F[t] = s * (1.0f / ((float)HH * (float)WW));
    }
    __syncthreads();

    {
        float psi = TWO_PI * (float)t * (1.0f / (float)HH);
        float d1c, d1s; __sincosf(psi, &d1s, &d1c);
        float d2c = d1c * d1c - d1s * d1s, d2s = 2.f * d1c * d1s;
        float d3c = d2c * d1c - d2s * d1s, d3s = d2c * d1s + d2s * d1c;
        float Dc[6] = { d3c,  d2c,  d1c,  1.f, d1c, d2c };
        float Ds[6] = { -d3s, -d2s, -d1s, 0.f, d1s, d2s };

        float* ggp = g_gg + (((size_t)bc * HH + t) * NK) * 2;
#pragma unroll
        for (int k = 0; k < 6; k++) {
            float gr = 0.f, gi = 0.f;
#pragma unroll
            for (int u = 0; u < 6; u++) {
                float Fr = F[(u * 6 + k) * 2 + 0];
                float Fi = F[(u * 6 + k) * 2 + 1];
                gr += Fr * Dc[u] - Fi * Ds[u];
                gi += Fr * Ds[u] + Fi * Dc[u];
            }
            ggp[k * 2 + 0] = gr;
            ggp[k * 2 + 1] = gi;
        }
    }
}

// ---------------------------------------------------------------------------
// Kernel 3: reconstruction + MLP + residual + clip.
// Thread handles 2 adjacent pixels packed in f32x2. 16 rows per block.
// grid (H/16, B) = (32, 32), block 256.
// ---------------------------------------------------------------------------
__device__ __forceinline__ float mlp_pixel(const float lp[3],
                                           const float W1r[8][3], const float B1r[8],
                                           const float W2r[3][8], const float B2r[3],
                                           int ch) {
    float hv[8];
#pragma unroll
    for (int j = 0; j < 8; j++) {
        float a = B1r[j];
        a = fmaf(W1r[j][0], lp[0], a);
        a = fmaf(W1r[j][1], lp[1], a);
        a = fmaf(W1r[j][2], lp[2], a);
        hv[j] = fmaxf(a, 0.f);
    }
    float y = B2r[ch] + lp[ch];
#pragma unroll
    for (int j = 0; j < 8; j++) y = fmaf(W2r[ch][j], hv[j], y);
    return fminf(fmaxf(y, 0.f), 1.f);
}

__global__ __launch_bounds__(256) void k3_final(const float* __restrict__ w1,
                                                const float* __restrict__ b1,
                                                const float* __restrict__ w2,
                                                const float* __restrict__ b2,
                                                float* __restrict__ out) {
    const int b  = blockIdx.y;
    const int h0 = blockIdx.x * R3ROWS;
    const int t  = threadIdx.x;   // pixel pair (2t, 2t+1)

    __shared__ u64 sg2[R3ROWS * 36];  // broadcast pairs (v,v): [(r*3+ch)*12 + k*2 + {re,im}]
    __shared__ float wt[64];

    for (int i = t; i < R3ROWS * 36; i += 256) {
        int r  = i / 36;
        int ch = (i % 36) / 12;
        int j  = i % 12;
        float v = g_gg[(((size_t)(b * 3 + ch) * HH) + (h0 + r)) * 12 + j];
        sg2[i] = pk(v, v);
    }
    if (t < 24)      wt[t]      = w1[t];
    else if (t < 32) wt[t]      = b1[t - 24];
    else if (t < 56) wt[t]      = w2[t - 32];
    else if (t < 59) wt[t]      = b2[t - 56];
    __syncthreads();

    float W1r[8][3], B1r[8], W2r[3][8], B2r[3];
#pragma unroll
    for (int j = 0; j < 8; j++) {
#pragma unroll
        for (int cc = 0; cc < 3; cc++) W1r[j][cc] = wt[j * 3 + cc];
        B1r[j] = wt[24 + j];
    }
#pragma unroll
    for (int cc = 0; cc < 3; cc++) {
#pragma unroll
        for (int j = 0; j < 8; j++) W2r[cc][j] = wt[32 + cc * 8 + j];
        B2r[cc] = wt[56 + cc];
    }

    const int w0 = 2 * t;
    float phi0 = TWO_PI * (float)w0 * (1.0f / (float)WW);
    float phi1 = TWO_PI * (float)(w0 + 1) * (1.0f / (float)WW);
    float c0, s0, c1, s1;
    __sincosf(phi0, &s0, &c0);
    __sincosf(phi1, &s1, &c1);
    u64 cr2  = pk(c0, c1);
    u64 ci2  = pk(s0, s1);
    u64 nci2 = neg2_(ci2);

#pragma unroll 4
    for (int r = 0; r < R3ROWS; ++r) {
        float lpA[3], lpB[3];
#pragma unroll
        for (int ch = 0; ch < 3; ch++) {
            const u64* g = &sg2[(r * 3 + ch) * 12];
            u64 ar = g[10], ai = g[11];          // k = 5
#pragma unroll
            for (int k = 4; k >= 0; --k) {
                u64 nr = fma2_(ar, cr2, fma2_(ai, nci2, g[2 * k]));
                u64 ni = fma2_(ar, ci2, fma2_(ai, cr2,  g[2 * k + 1]));
                ar = nr; ai = ni;
            }
            u64 m2 = fma2_(ar, ar, mul2_(ai, ai));
            float2 m = upk(m2);
            float m0 = fmaxf(m.x, 1e-30f), m1 = fmaxf(m.y, 1e-30f);
            lpA[ch] = m0 * __frsqrt_rn(m0);
            lpB[ch] = m1 * __frsqrt_rn(m1);
        }

#pragma unroll
        for (int ch = 0; ch < 3; ch++) {
            float2 yv;
            yv.x = mlp_pixel(lpA, W1r, B1r, W2r, B2r, ch);
            yv.y = mlp_pixel(lpB, W1r, B1r, W2r, B2r, ch);
            float2* orow = (float2*)(out + (((size_t)(b * 3 + ch) * HH) + (h0 + r)) * WW);
            orow[t] = yv;
        }
    }
}

// ---------------------------------------------------------------------------
extern "C" void kernel_launch(void* const* d_in, const int* in_sizes, int n_in,
                              void* d_out, int out_size) {
    const float* x  = (const float*)d_in[0];
    const float* w1 = (const float*)d_in[1];
    const float* b1 = (const float*)d_in[2];
    const float* w2 = (const float*)d_in[3];
    const float* b2 = (const float*)d_in[4];
    float* out = (float*)d_out;

    k1_coldft<<<dim3(NCHUNK, BB * CCH), 128>>>(x);
    k2_reduce<<<BB * CCH, 512>>>();
    k3_final<<<dim3(HH / R3ROWS, BB), 256>>>(w1, b1, w2, b2, out);
}

// round 6
// speedup vs baseline: 1.8405x; 1.0136x over previous
#include <cuda_runtime.h>
#include <math.h>

#define HH 512
#define WW 512
#define BB 32
#define CCH 3
#define NK 6
#define NCHUNK 16
#define CROWS 32          // HH / NCHUNK
#define R3ROWS 16
#define TWO_PI 6.283185307179586f

typedef unsigned long long u64;

__device__ __forceinline__ u64 pk(float lo, float hi) {
    u64 r; asm("mov.b64 %0,{%1,%2};" : "=l"(r) : "f"(lo), "f"(hi)); return r;
}
__device__ __forceinline__ float2 upk(u64 v) {
    float2 f; asm("mov.b64 {%0,%1},%2;" : "=f"(f.x), "=f"(f.y) : "l"(v)); return f;
}
__device__ __forceinline__ u64 fma2_(u64 a, u64 b, u64 c) {
    u64 d; asm("fma.rn.f32x2 %0,%1,%2,%3;" : "=l"(d) : "l"(a), "l"(b), "l"(c)); return d;
}
__device__ __forceinline__ u64 mul2_(u64 a, u64 b) {
    u64 d; asm("mul.rn.f32x2 %0,%1,%2;" : "=l"(d) : "l"(a), "l"(b)); return d;
}
__device__ __forceinline__ u64 neg2_(u64 a) { return a ^ 0x8000000080000000ULL; }

// Scratch (device globals — no allocation allowed)
__device__ float g_Fpart[BB * CCH * NCHUNK * 72];  // [bc][chunk][u*6+k][re,im]
__device__ float g_gg[BB * CCH * HH * NK * 2];     // [bc][h][k][re,im]

// ---------------------------------------------------------------------------
// Kernel 1: per (chunk,bc) block computes partial F[u][k] over a 32-row tile.
// Main loop packed with fma.rn.f32x2; twiddles pre-packed u64 in shared.
// Block 128 threads, thread = float4 of w. Grid (16, 96) = 1536 blocks.
// ---------------------------------------------------------------------------
__global__ __launch_bounds__(128) void k1_coldft(const float* __restrict__ x) {
    const int chunk = blockIdx.x;
    const int bc    = blockIdx.y;
    const int t     = threadIdx.x;
    const int h0    = chunk * CROWS;

    __shared__ __align__(16) u64 tw2[CROWS][12];   // [hl][2u]=(c,c), [2u+1]=(s,s)
    __shared__ float sm_part[4][72];

    for (int i = t; i < CROWS * 6; i += 128) {
        int hl = i / 6, u = i % 6;
        float a = -TWO_PI * (float)(h0 + hl) * (1.0f / (float)HH) * (float)(u - 3);
        float s, c; __sincosf(a, &s, &c);
        tw2[hl][2 * u]     = pk(c, c);
        tw2[hl][2 * u + 1] = pk(s, s);
    }
    __syncthreads();

    u64 cre01[6], cim01[6], cre23[6], cim23[6];
#pragma unroll
    for (int u = 0; u < 6; u++) { cre01[u] = 0ULL; cim01[u] = 0ULL; cre23[u] = 0ULL; cim23[u] = 0ULL; }

    const float4* xp = (const float4*)(x + (size_t)bc * HH * WW + (size_t)h0 * WW) + t;
#pragma unroll 8
    for (int hl = 0; hl < CROWS; ++hl) {
        float4 v = __ldg(xp + (size_t)hl * (WW / 4));
        u64 v01 = pk(v.x, v.y), v23 = pk(v.z, v.w);
#pragma unroll
        for (int u = 0; u < 6; u++) {
            u64 cc = tw2[hl][2 * u];
            u64 ss = tw2[hl][2 * u + 1];
            cre01[u] = fma2_(v01, cc, cre01[u]);
            cim01[u] = fma2_(v01, ss, cim01[u]);
            cre23[u] = fma2_(v23, cc, cre23[u]);
            cim23[u] = fma2_(v23, ss, cim23[u]);
        }
    }

    // unpack column sums to scalars
    float cre[6][4], cim[6][4];
#pragma unroll
    for (int u = 0; u < 6; u++) {
        float2 a = upk(cre01[u]); cre[u][0] = a.x; cre[u][1] = a.y;
        float2 b = upk(cre23[u]); cre[u][2] = b.x; cre[u][3] = b.y;
        float2 c = upk(cim01[u]); cim[u][0] = c.x; cim[u][1] = c.y;
        float2 d = upk(cim23[u]); cim[u][2] = d.x; cim[u][3] = d.y;
    }

    // E_k[w] = e^{-i (k-3) phi_w} for this thread's 4 w's
    float Ec[4][6], Es[4][6];
#pragma unroll
    for (int j = 0; j < 4; j++) {
        float phi = TWO_PI * (float)(4 * t + j) * (1.0f / (float)WW);
        float c1, s1; __sincosf(phi, &s1, &c1);
        float c2 = c1 * c1 - s1 * s1, s2 = 2.f * c1 * s1;
        float c3 = c2 * c1 - s2 * s1, s3 = c2 * s1 + s2 * c1;
        Ec[j][0] = c3; Es[j][0] = s3;
        Ec[j][1] = c2; Es[j][1] = s2;
        Ec[j][2] = c1; Es[j][2] = s1;
        Ec[j][3] = 1.f; Es[j][3] = 0.f;
        Ec[j][4] = c1; Es[j][4] = -s1;
        Ec[j][5] = c2; Es[j][5] = -s2;
    }

    const int wid = t >> 5, lid = t & 31;
#pragma unroll
    for (int u = 0; u < 6; u++) {
        float fr[6], fi[6];
#pragma unroll
        for (int k = 0; k < 6; k++) { fr[k] = 0.f; fi[k] = 0.f; }
#pragma unroll
        for (int j = 0; j < 4; j++) {
            float gr = cre[u][j], gi = cim[u][j];
#pragma unroll
            for (int k = 0; k < 6; k++) {
                fr[k] = fmaf(gr, Ec[j][k], fmaf(-gi, Es[j][k], fr[k]));
                fi[k] = fmaf(gr, Es[j][k], fmaf( gi, Ec[j][k], fi[k]));
            }
        }
#pragma unroll
        for (int off = 16; off >= 1; off >>= 1) {
#pragma unroll
            for (int k = 0; k < 6; k++) {
                fr[k] += __shfl_xor_sync(0xFFFFFFFFu, fr[k], off);
                fi[k] += __shfl_xor_sync(0xFFFFFFFFu, fi[k], off);
            }
        }
        if (lid == 0) {
#pragma unroll
            for (int k = 0; k < 6; k++) {
                sm_part[wid][(u * 6 + k) * 2 + 0] = fr[k];
                sm_part[wid][(u * 6 + k) * 2 + 1] = fi[k];
            }
        }
    }
    __syncthreads();

    if (t < 72) {
        float s = sm_part[0][t] + sm_part[1][t] + sm_part[2][t] + sm_part[3][t];
        g_Fpart[((size_t)bc * NCHUNK + chunk) * 72 + t] = s;
    }
}

// ---------------------------------------------------------------------------
// Kernel 2: per (b,c): sum chunk partials -> F (normalized), then
// g_gg[h][k] = sum_u F[u][k] e^{+2pi i (u-3) h/512}.  grid 96, block 512.
// ---------------------------------------------------------------------------
__global__ __launch_bounds__(512) void k2_reduce() {
    const int bc = blockIdx.x;
    const int t  = threadIdx.x;

    __shared__ float F[72];

    if (t < 72) {
        const float* fp = g_Fpart + (size_t)bc * NCHUNK * 72 + t;
        float s = 0.f;
#pragma unroll
        for (int c = 0; c < NCHUNK; c++) s += fp[c * 72];
        F[t] = s * (1.0f / ((float)HH * (float)WW));
    }
    __syncthreads();

    {
        float psi = TWO_PI * (float)t * (1.0f / (float)HH);
        float d1c, d1s; __sincosf(psi, &d1s, &d1c);
        float d2c = d1c * d1c - d1s * d1s, d2s = 2.f * d1c * d1s;
        float d3c = d2c * d1c - d2s * d1s, d3s = d2c * d1s + d2s * d1c;
        float Dc[6] = { d3c,  d2c,  d1c,  1.f, d1c, d2c };
        float Ds[6] = { -d3s, -d2s, -d1s, 0.f, d1s, d2s };

        float* ggp = g_gg + (((size_t)bc * HH + t) * NK) * 2;
#pragma unroll
        for (int k = 0; k < 6; k++) {
            float gr = 0.f, gi = 0.f;
#pragma unroll
            for (int u = 0; u < 6; u++) {
                float Fr = F[(u * 6 + k) * 2 + 0];
                float Fi = F[(u * 6 + k) * 2 + 1];
                gr += Fr * Dc[u] - Fi * Ds[u];
                gi += Fr * Ds[u] + Fi * Dc[u];
            }
            ggp[k * 2 + 0] = gr;
            ggp[k * 2 + 1] = gi;
        }
    }
}

// ---------------------------------------------------------------------------
// Kernel 3: reconstruction + MLP + residual + clip.
// Thread handles 2 adjacent pixels packed in f32x2 for the Horner part;
// MLP hidden layer computed ONCE per pixel (channel-independent).
// grid (H/16, B) = (32, 32), block 256.
// ---------------------------------------------------------------------------
__global__ __launch_bounds__(256) void k3_final(const float* __restrict__ w1,
                                                const float* __restrict__ b1,
                                                const float* __restrict__ w2,
                                                const float* __restrict__ b2,
                                                float* __restrict__ out) {
    const int b  = blockIdx.y;
    const int h0 = blockIdx.x * R3ROWS;
    const int t  = threadIdx.x;   // pixel pair (2t, 2t+1)

    __shared__ u64 sg2[R3ROWS * 36];  // broadcast pairs (v,v): [(r*3+ch)*12 + k*2 + {re,im}]
    __shared__ float wt[64];

    for (int i = t; i < R3ROWS * 36; i += 256) {
        int r  = i / 36;
        int ch = (i % 36) / 12;
        int j  = i % 12;
        float v = g_gg[(((size_t)(b * 3 + ch) * HH) + (h0 + r)) * 12 + j];
        sg2[i] = pk(v, v);
    }
    if (t < 24)      wt[t] = w1[t];
    else if (t < 32) wt[t] = b1[t - 24];
    else if (t < 56) wt[t] = w2[t - 32];
    else if (t < 59) wt[t] = b2[t - 56];
    __syncthreads();

    float W1r[8][3], B1r[8], W2r[3][8], B2r[3];
#pragma unroll
    for (int j = 0; j < 8; j++) {
#pragma unroll
        for (int cc = 0; cc < 3; cc++) W1r[j][cc] = wt[j * 3 + cc];
        B1r[j] = wt[24 + j];
    }
#pragma unroll
    for (int cc = 0; cc < 3; cc++) {
#pragma unroll
        for (int j = 0; j < 8; j++) W2r[cc][j] = wt[32 + cc * 8 + j];
        B2r[cc] = wt[56 + cc];
    }

    const int w0 = 2 * t;
    float phi0 = TWO_PI * (float)w0 * (1.0f / (float)WW);
    float phi1 = TWO_PI * (float)(w0 + 1) * (1.0f / (float)WW);
    float c0, s0, c1, s1;
    __sincosf(phi0, &s0, &c0);
    __sincosf(phi1, &s1, &c1);
    u64 cr2  = pk(c0, c1);
    u64 ci2  = pk(s0, s1);
    u64 nci2 = neg2_(ci2);

#pragma unroll 4
    for (int r = 0; r < R3ROWS; ++r) {
        float lpA[3], lpB[3];
#pragma unroll
        for (int ch = 0; ch < 3; ch++) {
            const u64* g = &sg2[(r * 3 + ch) * 12];
            u64 ar = g[10], ai = g[11];          // k = 5
#pragma unroll
            for (int k = 4; k >= 0; --k) {
                u64 nr = fma2_(ar, cr2, fma2_(ai, nci2, g[2 * k]));
                u64 ni = fma2_(ar, ci2, fma2_(ai, cr2,  g[2 * k + 1]));
                ar = nr; ai = ni;
            }
            u64 m2 = fma2_(ar, ar, mul2_(ai, ai));
            float2 m = upk(m2);
            float m0 = fmaxf(m.x, 1e-30f), m1 = fmaxf(m.y, 1e-30f);
            lpA[ch] = m0 * __frsqrt_rn(m0);
            lpB[ch] = m1 * __frsqrt_rn(m1);
        }

        // hidden layer once per pixel (channel-independent)
        float hA[8], hB[8];
#pragma unroll
        for (int j = 0; j < 8; j++) {
            float aA = B1r[j], aB = B1r[j];
            aA = fmaf(W1r[j][0], lpA[0], aA);  aB = fmaf(W1r[j][0], lpB[0], aB);
            aA = fmaf(W1r[j][1], lpA[1], aA);  aB = fmaf(W1r[j][1], lpB[1], aB);
            aA = fmaf(W1r[j][2], lpA[2], aA);  aB = fmaf(W1r[j][2], lpB[2], aB);
            hA[j] = fmaxf(aA, 0.f);            hB[j] = fmaxf(aB, 0.f);
        }

#pragma unroll
        for (int ch = 0; ch < 3; ch++) {
            float yA = B2r[ch] + lpA[ch];
            float yB = B2r[ch] + lpB[ch];
#pragma unroll
            for (int j = 0; j < 8; j++) {
                yA = fmaf(W2r[ch][j], hA[j], yA);
                yB = fmaf(W2r[ch][j], hB[j], yB);
            }
            float2 yv;
            yv.x = __saturatef(yA);
            yv.y = __saturatef(yB);
            float2* orow = (float2*)(out + (((size_t)(b * 3 + ch) * HH) + (h0 + r)) * WW);
            orow[t] = yv;
        }
    }
}

// ---------------------------------------------------------------------------
extern "C" void kernel_launch(void* const* d_in, const int* in_sizes, int n_in,
                              void* d_out, int out_size) {
    const float* x  = (const float*)d_in[0];
    const float* w1 = (const float*)d_in[1];
    const float* b1 = (const float*)d_in[2];
    const float* w2 = (const float*)d_in[3];
    const float* b2 = (const float*)d_in[4];
    float* out = (float*)d_out;

    k1_coldft<<<dim3(NCHUNK, BB * CCH), 128>>>(x);
    k2_reduce<<<BB * CCH, 512>>>();
    k3_final<<<dim3(HH / R3ROWS, BB), 256>>>(w1, b1, w2, b2, out);
}

// round 7
// speedup vs baseline: 1.8669x; 1.0144x over previous
#include <cuda_runtime.h>
#include <math.h>

#define HH 512
#define WW 512
#define BB 32
#define CCH 3
#define NK 6
#define NCHUNK 8
#define CROWS 64          // HH / NCHUNK
#define R3ROWS 8
#define TWO_PI 6.283185307179586f

typedef unsigned long long u64;

__device__ __forceinline__ u64 pk(float lo, float hi) {
    u64 r; asm("mov.b64 %0,{%1,%2};" : "=l"(r) : "f"(lo), "f"(hi)); return r;
}
__device__ __forceinline__ float2 upk(u64 v) {
    float2 f; asm("mov.b64 {%0,%1},%2;" : "=f"(f.x), "=f"(f.y) : "l"(v)); return f;
}
__device__ __forceinline__ u64 fma2_(u64 a, u64 b, u64 c) {
    u64 d; asm("fma.rn.f32x2 %0,%1,%2,%3;" : "=l"(d) : "l"(a), "l"(b), "l"(c)); return d;
}
__device__ __forceinline__ u64 mul2_(u64 a, u64 b) {
    u64 d; asm("mul.rn.f32x2 %0,%1,%2;" : "=l"(d) : "l"(a), "l"(b)); return d;
}
__device__ __forceinline__ u64 neg2_(u64 a) { return a ^ 0x8000000080000000ULL; }

// Scratch (device globals — no allocation allowed)
__device__ float g_Fpart[BB * CCH * NCHUNK * 72];  // [bc][chunk][u*6+k][re,im]
__device__ float g_gg[BB * CCH * HH * NK * 2];     // [bc][h][k][re,im]

// ---------------------------------------------------------------------------
// Kernel 1: per (chunk,bc) block computes partial F[u][k] over a 64-row tile.
// Thread = 2 adjacent w's (one f32x2 lane pair). Block 256, grid (8,96)=768.
// Low register count -> 3 resident blocks/SM.
// ---------------------------------------------------------------------------
__global__ __launch_bounds__(256, 3) void k1_coldft(const float* __restrict__ x) {
    const int chunk = blockIdx.x;
    const int bc    = blockIdx.y;
    const int t     = threadIdx.x;
    const int h0    = chunk * CROWS;

    __shared__ __align__(16) u64 tw2[CROWS][12];   // [hl][2u]=(c,c), [2u+1]=(s,s)
    __shared__ float sm_part[8][72];

    for (int i = t; i < CROWS * 6; i += 256) {
        int hl = i / 6, u = i % 6;
        float a = -TWO_PI * (float)(h0 + hl) * (1.0f / (float)HH) * (float)(u - 3);
        float s, c; __sincosf(a, &s, &c);
        tw2[hl][2 * u]     = pk(c, c);
        tw2[hl][2 * u + 1] = pk(s, s);
    }
    __syncthreads();

    u64 cre2[6], cim2[6];
#pragma unroll
    for (int u = 0; u < 6; u++) { cre2[u] = 0ULL; cim2[u] = 0ULL; }

    const float2* xp = (const float2*)(x + (size_t)bc * HH * WW + (size_t)h0 * WW) + t;
#pragma unroll 8
    for (int hl = 0; hl < CROWS; ++hl) {
        float2 v = __ldg(xp + (size_t)hl * (WW / 2));
        u64 v2 = pk(v.x, v.y);
#pragma unroll
        for (int u = 0; u < 6; u++) {
            cre2[u] = fma2_(v2, tw2[hl][2 * u],     cre2[u]);
            cim2[u] = fma2_(v2, tw2[hl][2 * u + 1], cim2[u]);
        }
    }

    // E_k[w] = e^{-i (k-3) phi_w} for this thread's 2 w's, packed
    u64 Ec2[6], Es2[6];
    {
        float cA[6], sA[6], cB[6], sB[6];
#pragma unroll
        for (int j = 0; j < 2; j++) {
            float phi = TWO_PI * (float)(2 * t + j) * (1.0f / (float)WW);
            float c1, s1; __sincosf(phi, &s1, &c1);
            float c2 = c1 * c1 - s1 * s1, s2 = 2.f * c1 * s1;
            float c3 = c2 * c1 - s2 * s1, s3 = c2 * s1 + s2 * c1;
            float* C = j ? cB : cA; float* S = j ? sB : sA;
            C[0] = c3; S[0] = s3;
            C[1] = c2; S[1] = s2;
            C[2] = c1; S[2] = s1;
            C[3] = 1.f; S[3] = 0.f;
            C[4] = c1; S[4] = -s1;
            C[5] = c2; S[5] = -s2;
        }
#pragma unroll
        for (int k = 0; k < 6; k++) { Ec2[k] = pk(cA[k], cB[k]); Es2[k] = pk(sA[k], sB[k]); }
    }

    const int wid = t >> 5, lid = t & 31;
#pragma unroll
    for (int u = 0; u < 6; u++) {
        u64 gr2 = cre2[u], gi2 = cim2[u], ngi2 = neg2_(cim2[u]);
        float fr[6], fi[6];
#pragma unroll
        for (int k = 0; k < 6; k++) {
            u64 fr2 = fma2_(gr2, Ec2[k], mul2_(ngi2, Es2[k]));
            u64 fi2 = fma2_(gr2, Es2[k], mul2_(gi2,  Ec2[k]));
            float2 a = upk(fr2); fr[k] = a.x + a.y;
            float2 b = upk(fi2); fi[k] = b.x + b.y;
        }
#pragma unroll
        for (int off = 16; off >= 1; off >>= 1) {
#pragma unroll
            for (int k = 0; k < 6; k++) {
                fr[k] += __shfl_xor_sync(0xFFFFFFFFu, fr[k], off);
                fi[k] += __shfl_xor_sync(0xFFFFFFFFu, fi[k], off);
            }
        }
        if (lid == 0) {
#pragma unroll
            for (int k = 0; k < 6; k++) {
                sm_part[wid][(u * 6 + k) * 2 + 0] = fr[k];
                sm_part[wid][(u * 6 + k) * 2 + 1] = fi[k];
            }
        }
    }
    __syncthreads();

    if (t < 72) {
        float s = 0.f;
#pragma unroll
        for (int q = 0; q < 8; q++) s += sm_part[q][t];
        g_Fpart[((size_t)bc * NCHUNK + chunk) * 72 + t] = s;
    }
}

// ---------------------------------------------------------------------------
// Kernel 2: per (b,c): sum chunk partials -> F (normalized), then
// g_gg[h][k] = sum_u F[u][k] e^{+2pi i (u-3) h/512}.  grid 96, block 512.
// ---------------------------------------------------------------------------
__global__ __launch_bounds__(512) void k2_reduce() {
    const int bc = blockIdx.x;
    const int t  = threadIdx.x;

    __shared__ float F[72];

    if (t < 72) {
        const float* fp = g_Fpart + (size_t)bc * NCHUNK * 72 + t;
        float s = 0.f;
#pragma unroll
        for (int c = 0; c < NCHUNK; c++) s += fp[c * 72];
        F[t] = s * (1.0f / ((float)HH * (float)WW));
    }
    __syncthreads();

    {
        float psi = TWO_PI * (float)t * (1.0f / (float)HH);
        float d1c, d1s; __sincosf(psi, &d1s, &d1c);
        float d2c = d1c * d1c - d1s * d1s, d2s = 2.f * d1c * d1s;
        float d3c = d2c * d1c - d2s * d1s, d3s = d2c * d1s + d2s * d1c;
        float Dc[6] = { d3c,  d2c,  d1c,  1.f, d1c, d2c };
        float Ds[6] = { -d3s, -d2s, -d1s, 0.f, d1s, d2s };

        float* ggp = g_gg + (((size_t)bc * HH + t) * NK) * 2;
#pragma unroll
        for (int k = 0; k < 6; k++) {
            float gr = 0.f, gi = 0.f;
#pragma unroll
            for (int u = 0; u < 6; u++) {
                float Fr = F[(u * 6 + k) * 2 + 0];
                float Fi = F[(u * 6 + k) * 2 + 1];
                gr += Fr * Dc[u] - Fi * Ds[u];
                gi += Fr * Ds[u] + Fi * Dc[u];
            }
            ggp[k * 2 + 0] = gr;
            ggp[k * 2 + 1] = gi;
        }
    }
}

// ---------------------------------------------------------------------------
// Kernel 3: reconstruction + MLP + residual + clip.
// Thread handles 2 adjacent pixels packed in f32x2 for the Horner part.
// grid (H/8, B) = (64, 32), block 256.
// ---------------------------------------------------------------------------
__global__ __launch_bounds__(256) void k3_final(const float* __restrict__ w1,
                                                const float* __restrict__ b1,
                                                const float* __restrict__ w2,
                                                const float* __restrict__ b2,
                                                float* __restrict__ out) {
    const int b  = blockIdx.y;
    const int h0 = blockIdx.x * R3ROWS;
    const int t  = threadIdx.x;   // pixel pair (2t, 2t+1)

    __shared__ __align__(16) u64 sg2[R3ROWS * 36];  // (v,v) pairs: [(r*3+ch)*12 + k*2 + {re,im}]
    __shared__ float wt[64];

    for (int i = t; i < R3ROWS * 36; i += 256) {
        int r  = i / 36;
        int ch = (i % 36) / 12;
        int j  = i % 12;
        float v = g_gg[(((size_t)(b * 3 + ch) * HH) + (h0 + r)) * 12 + j];
        sg2[i] = pk(v, v);
    }
    if (t < 24)      wt[t] = w1[t];
    else if (t < 32) wt[t] = b1[t - 24];
    else if (t < 56) wt[t] = w2[t - 32];
    else if (t < 59) wt[t] = b2[t - 56];
    __syncthreads();

    float W1r[8][3], B1r[8], W2r[3][8], B2r[3];
#pragma unroll
    for (int j = 0; j < 8; j++) {
#pragma unroll
        for (int cc = 0; cc < 3; cc++) W1r[j][cc] = wt[j * 3 + cc];
        B1r[j] = wt[24 + j];
    }
#pragma unroll
    for (int cc = 0; cc < 3; cc++) {
#pragma unroll
        for (int j = 0; j < 8; j++) W2r[cc][j] = wt[32 + cc * 8 + j];
        B2r[cc] = wt[56 + cc];
    }

    const int w0 = 2 * t;
    float phi0 = TWO_PI * (float)w0 * (1.0f / (float)WW);
    float phi1 = TWO_PI * (float)(w0 + 1) * (1.0f / (float)WW);
    float c0, s0, c1, s1;
    __sincosf(phi0, &s0, &c0);
    __sincosf(phi1, &s1, &c1);
    u64 cr2  = pk(c0, c1);
    u64 ci2  = pk(s0, s1);
    u64 nci2 = neg2_(ci2);

#pragma unroll
    for (int r = 0; r < R3ROWS; ++r) {
        float lpA[3], lpB[3];
#pragma unroll
        for (int ch = 0; ch < 3; ch++) {
            const ulonglong2* g = (const ulonglong2*)&sg2[(r * 3 + ch) * 12];
            ulonglong2 g5 = g[5];
            u64 ar = g5.x, ai = g5.y;          // k = 5
#pragma unroll
            for (int k = 4; k >= 0; --k) {
                ulonglong2 gk = g[k];          // LDS.128: (re, im) pair
                u64 nr = fma2_(ar, cr2, fma2_(ai, nci2, gk.x));
                u64 ni = fma2_(ar, ci2, fma2_(ai, cr2,  gk.y));
                ar = nr; ai = ni;
            }
            u64 m2 = fma2_(ar, ar, mul2_(ai, ai));
            float2 m = upk(m2);
            float m0 = fmaxf(m.x, 1e-30f), m1 = fmaxf(m.y, 1e-30f);
            lpA[ch] = m0 * __frsqrt_rn(m0);
            lpB[ch] = m1 * __frsqrt_rn(m1);
        }

        // hidden layer once per pixel (channel-independent)
        float hA[8], hB[8];
#pragma unroll
        for (int j = 0; j < 8; j++) {
            float aA = B1r[j], aB = B1r[j];
            aA = fmaf(W1r[j][0], lpA[0], aA);  aB = fmaf(W1r[j][0], lpB[0], aB);
            aA = fmaf(W1r[j][1], lpA[1], aA);  aB = fmaf(W1r[j][1], lpB[1], aB);
            aA = fmaf(W1r[j][2], lpA[2], aA);  aB = fmaf(W1r[j][2], lpB[2], aB);
            hA[j] = fmaxf(aA, 0.f);            hB[j] = fmaxf(aB, 0.f);
        }

#pragma unroll
        for (int ch = 0; ch < 3; ch++) {
            float yA = B2r[ch] + lpA[ch];
            float yB = B2r[ch] + lpB[ch];
#pragma unroll
            for (int j = 0; j < 8; j++) {
                yA = fmaf(W2r[ch][j], hA[j], yA);
                yB = fmaf(W2r[ch][j], hB[j], yB);
            }
            float2 yv;
            yv.x = __saturatef(yA);
            yv.y = __saturatef(yB);
            float2* orow = (float2*)(out + (((size_t)(b * 3 + ch) * HH) + (h0 + r)) * WW);
            orow[t] = yv;
        }
    }
}

// ---------------------------------------------------------------------------
extern "C" void kernel_launch(void* const* d_in, const int* in_sizes, int n_in,
                              void* d_out, int out_size) {
    const float* x  = (const float*)d_in[0];
    const float* w1 = (const float*)d_in[1];
    const float* b1 = (const float*)d_in[2];
    const float* w2 = (const float*)d_in[3];
    const float* b2 = (const float*)d_in[4];
    float* out = (float*)d_out;

    k1_coldft<<<dim3(NCHUNK, BB * CCH), 256>>>(x);
    k2_reduce<<<BB * CCH, 512>>>();
    k3_final<<<dim3(HH / R3ROWS, BB), 256>>>(w1, b1, w2, b2, out);
}

// round 9
// speedup vs baseline: 1.9479x; 1.0434x over previous
#include <cuda_runtime.h>
#include <math.h>

#define HH 512
#define WW 512
#define BB 32
#define CCH 3
#define NK 6
#define NCHUNK 8
#define CROWS 64          // HH / NCHUNK
#define R3ROWS 8
#define TWO_PI 6.283185307179586f

typedef unsigned long long u64;

__device__ __forceinline__ u64 pk(float lo, float hi) {
    u64 r; asm("mov.b64 %0,{%1,%2};" : "=l"(r) : "f"(lo), "f"(hi)); return r;
}
__device__ __forceinline__ float2 upk(u64 v) {
    float2 f; asm("mov.b64 {%0,%1},%2;" : "=f"(f.x), "=f"(f.y) : "l"(v)); return f;
}
__device__ __forceinline__ u64 fma2_(u64 a, u64 b, u64 c) {
    u64 d; asm("fma.rn.f32x2 %0,%1,%2,%3;" : "=l"(d) : "l"(a), "l"(b), "l"(c)); return d;
}
__device__ __forceinline__ u64 mul2_(u64 a, u64 b) {
    u64 d; asm("mul.rn.f32x2 %0,%1,%2;" : "=l"(d) : "l"(a), "l"(b)); return d;
}
__device__ __forceinline__ u64 add2_(u64 a, u64 b) {
    u64 d; asm("add.rn.f32x2 %0,%1,%2;" : "=l"(d) : "l"(a), "l"(b)); return d;
}
__device__ __forceinline__ u64 neg2_(u64 a) { return a ^ 0x8000000080000000ULL; }

// Scratch (device globals — no allocation allowed)
__device__ float g_Fpart[BB * CCH * NCHUNK * 72];  // [bc][chunk][u*6+k][re,im]
__device__ float g_gg[BB * CCH * HH * NK * 2];     // [bc][h][k][re,im]

// ---------------------------------------------------------------------------
// Kernel 1: partial F[u][k] over a 64-row tile. Real-input symmetry:
// only 7 accumulators (S0, Cr1..3, Ci1..3) and 3 complex twiddles per row.
// Thread = float4 of w. Block 128, grid (8, 96) = 768 blocks.
// ---------------------------------------------------------------------------
__global__ __launch_bounds__(128) void k1_coldft(const float* __restrict__ x) {
    const int chunk = blockIdx.x;
    const int bc    = blockIdx.y;
    const int t     = threadIdx.x;
    const int h0    = chunk * CROWS;

    __shared__ __align__(16) u64 twc[CROWS][3], tws[CROWS][3]; // (c,c) / (s,s) for K=1..3
    __shared__ float sm_part[4][72];

    for (int i = t; i < CROWS * 3; i += 128) {
        int hl = i / 3, K = (i % 3) + 1;
        float a = TWO_PI * (float)(h0 + hl) * (1.0f / (float)HH) * (float)K;
        float s, c; __sincosf(a, &s, &c);
        twc[hl][K - 1] = pk(c, c);
        tws[hl][K - 1] = pk(s, s);
    }
    __syncthreads();

    // packed accumulators: [0] = w pair (0,1), [1] = w pair (2,3)
    u64 S0[2] = {0ULL, 0ULL};
    u64 Cr[3][2], Ci[3][2];
#pragma unroll
    for (int K = 0; K < 3; K++) { Cr[K][0] = Cr[K][1] = 0ULL; Ci[K][0] = Ci[K][1] = 0ULL; }

    const float4* xp = (const float4*)(x + (size_t)bc * HH * WW + (size_t)h0 * WW) + t;
#pragma unroll 8
    for (int hl = 0; hl < CROWS; ++hl) {
        float4 v = __ldg(xp + (size_t)hl * (WW / 4));
        u64 v01 = pk(v.x, v.y), v23 = pk(v.z, v.w);
        S0[0] = add2_(S0[0], v01);
        S0[1] = add2_(S0[1], v23);
#pragma unroll
        for (int K = 0; K < 3; K++) {
            u64 cc = twc[hl][K], ss = tws[hl][K];
            Cr[K][0] = fma2_(v01, cc, Cr[K][0]);
            Ci[K][0] = fma2_(v01, ss, Ci[K][0]);
            Cr[K][1] = fma2_(v23, cc, Cr[K][1]);
            Ci[K][1] = fma2_(v23, ss, Ci[K][1]);
        }
    }

    // reconstruct full column sums: cre[u][j], cim[u][j]
    // note twiddle angle used +K sign; column DFT needs e^{-2pi i (u-3) h/512}:
    //   u = 3-K  -> coefficient e^{+iKth} = (c, +s)  => (Cr, +Ci)
    //   u = 3+K  -> coefficient e^{-iKth} = (c, -s)  => (Cr, -Ci)
    float cre[6][4], cim[6][4];
    {
        float2 a0 = upk(S0[0]), a1 = upk(S0[1]);
        cre[3][0] = a0.x; cre[3][1] = a0.y; cre[3][2] = a1.x; cre[3][3] = a1.y;
        cim[3][0] = cim[3][1] = cim[3][2] = cim[3][3] = 0.f;
#pragma unroll
        for (int K = 1; K <= 3; K++) {
            float2 r0 = upk(Cr[K - 1][0]), r1 = upk(Cr[K - 1][1]);
            float2 i0 = upk(Ci[K - 1][0]), i1 = upk(Ci[K - 1][1]);
            float rv[4] = { r0.x, r0.y, r1.x, r1.y };
            float iv[4] = { i0.x, i0.y, i1.x, i1.y };
            int um = 3 - K, up = 3 + K;
#pragma unroll
            for (int j = 0; j < 4; j++) {
                cre[um][j] = rv[j]; cim[um][j] = iv[j];
                if (up < 6) { cre[up][j] = rv[j]; cim[up][j] = -iv[j]; }
            }
        }
    }

    // E_k[w] = e^{-i (k-3) phi_w} for this thread's 4 w's
    float Ec[4][6], Es[4][6];
#pragma unroll
    for (int j = 0; j < 4; j++) {
        float phi = TWO_PI * (float)(4 * t + j) * (1.0f / (float)WW);
        float c1, s1; __sincosf(phi, &s1, &c1);
        float c2 = c1 * c1 - s1 * s1, s2 = 2.f * c1 * s1;
        float c3 = c2 * c1 - s2 * s1, s3 = c2 * s1 + s2 * c1;
        Ec[j][0] = c3; Es[j][0] = s3;
        Ec[j][1] = c2; Es[j][1] = s2;
        Ec[j][2] = c1; Es[j][2] = s1;
        Ec[j][3] = 1.f; Es[j][3] = 0.f;
        Ec[j][4] = c1; Es[j][4] = -s1;
        Ec[j][5] = c2; Es[j][5] = -s2;
    }

    const int wid = t >> 5, lid = t & 31;
#pragma unroll
    for (int u = 0; u < 6; u++) {
        float fr[6], fi[6];
#pragma unroll
        for (int k = 0; k < 6; k++) { fr[k] = 0.f; fi[k] = 0.f; }
#pragma unroll
        for (int j = 0; j < 4; j++) {
            float gr = cre[u][j], gi = cim[u][j];
#pragma unroll
            for (int k = 0; k < 6; k++) {
                fr[k] = fmaf(gr, Ec[j][k], fmaf(-gi, Es[j][k], fr[k]));
                fi[k] = fmaf(gr, Es[j][k], fmaf( gi, Ec[j][k], fi[k]));
            }
        }
#pragma unroll
        for (int off = 16; off >= 1; off >>= 1) {
#pragma unroll
            for (int k = 0; k < 6; k++) {
                fr[k] += __shfl_xor_sync(0xFFFFFFFFu, fr[k], off);
                fi[k] += __shfl_xor_sync(0xFFFFFFFFu, fi[k], off);
            }
        }
        if (lid == 0) {
#pragma unroll
            for (int k = 0; k < 6; k++) {
                sm_part[wid][(u * 6 + k) * 2 + 0] = fr[k];
                sm_part[wid][(u * 6 + k) * 2 + 1] = fi[k];
            }
        }
    }
    __syncthreads();

    if (t < 72) {
        float s = sm_part[0][t] + sm_part[1][t] + sm_part[2][t] + sm_part[3][t];
        g_Fpart[((size_t)bc * NCHUNK + chunk) * 72 + t] = s;
    }
}

// ---------------------------------------------------------------------------
// Kernel 2: per (b,c): sum chunk partials -> F (normalized), then
// g_gg[h][k] = sum_u F[u][k] e^{+2pi i (u-3) h/512}.  grid 96, block 512.
// ---------------------------------------------------------------------------
__global__ __launch_bounds__(512) void k2_reduce() {
    const int bc = blockIdx.x;
    const int t  = threadIdx.x;

    __shared__ float F[72];

    if (t < 72) {
        const float* fp = g_Fpart + (size_t)bc * NCHUNK * 72 + t;
        float s = 0.f;
#pragma unroll
        for (int c = 0; c < NCHUNK; c++) s += fp[c * 72];
        F[t] = s * (1.0f / ((float)HH * (float)WW));
    }
    __syncthreads();

    {
        float psi = TWO_PI * (float)t * (1.0f / (float)HH);
        float d1c, d1s; __sincosf(psi, &d1s, &d1c);
        float d2c = d1c * d1c - d1s * d1s, d2s = 2.f * d1c * d1s;
        float d3c = d2c * d1c - d2s * d1s, d3s = d2c * d1s + d2s * d1c;
        float Dc[6] = { d3c,  d2c,  d1c,  1.f, d1c, d2c };
        float Ds[6] = { -d3s, -d2s, -d1s, 0.f, d1s, d2s };

        float* ggp = g_gg + (((size_t)bc * HH + t) * NK) * 2;
#pragma unroll
        for (int k = 0; k < 6; k++) {
            float gr = 0.f, gi = 0.f;
#pragma unroll
            for (int u = 0; u < 6; u++) {
                float Fr = F[(u * 6 + k) * 2 + 0];
                float Fi = F[(u * 6 + k) * 2 + 1];
                gr += Fr * Dc[u] - Fi * Ds[u];
                gi += Fr * Ds[u] + Fi * Dc[u];
            }
            ggp[k * 2 + 0] = gr;
            ggp[k * 2 + 1] = gi;
        }
    }
}

// ---------------------------------------------------------------------------
// Kernel 3: reconstruction + MLP + residual + clip.
// Direct 6-term dot product against precomputed E^k (hoisted, packed f32x2)
// instead of serial Horner -> 6 independent chains, latency-tolerant.
// Thread = 2 adjacent pixels. grid (H/8, B) = (64, 32), block 256.
// ---------------------------------------------------------------------------
__global__ __launch_bounds__(256) void k3_final(const float* __restrict__ w1,
                                                const float* __restrict__ b1,
                                                const float* __restrict__ w2,
                                                const float* __restrict__ b2,
                                                float* __restrict__ out) {
    const int b  = blockIdx.y;
    const int h0 = blockIdx.x * R3ROWS;
    const int t  = threadIdx.x;   // pixel pair (2t, 2t+1)

    __shared__ __align__(16) u64 sg2[R3ROWS * 36];  // (v,v) pairs: [(r*3+ch)*12 + k*2 + {re,im}]
    __shared__ float wt[64];

    for (int i = t; i < R3ROWS * 36; i += 256) {
        int r  = i / 36;
        int ch = (i % 36) / 12;
        int j  = i % 12;
        float v = g_gg[(((size_t)(b * 3 + ch) * HH) + (h0 + r)) * 12 + j];
        sg2[i] = pk(v, v);
    }
    if (t < 24)      wt[t] = w1[t];
    else if (t < 32) wt[t] = b1[t - 24];
    else if (t < 56) wt[t] = w2[t - 32];
    else if (t < 59) wt[t] = b2[t - 56];
    __syncthreads();

    float W1r[8][3], B1r[8], W2r[3][8], B2r[3];
#pragma unroll
    for (int j = 0; j < 8; j++) {
#pragma unroll
        for (int cc = 0; cc < 3; cc++) W1r[j][cc] = wt[j * 3 + cc];
        B1r[j] = wt[24 + j];
    }
#pragma unroll
    for (int cc = 0; cc < 3; cc++) {
#pragma unroll
        for (int j = 0; j < 8; j++) W2r[cc][j] = wt[32 + cc * 8 + j];
        B2r[cc] = wt[56 + cc];
    }

    // E^k for k=1..5, packed for the 2 pixels (hoisted out of the row loop)
    u64 Ec[6], Es[6];
    {
        const int w0 = 2 * t;
        float cA, sA, cB, sB;
        __sincosf(TWO_PI * (float)w0       * (1.0f / (float)WW), &sA, &cA);
        __sincosf(TWO_PI * (float)(w0 + 1) * (1.0f / (float)WW), &sB, &cB);
        u64 e1c = pk(cA, cB), e1s = pk(sA, sB);
        Ec[1] = e1c; Es[1] = e1s;
#pragma unroll
        for (int k = 2; k <= 5; k++) {
            Ec[k] = fma2_(Ec[k - 1], e1c, neg2_(mul2_(Es[k - 1], e1s)));
            Es[k] = fma2_(Ec[k - 1], e1s, mul2_(Es[k - 1], e1c));
        }
    }

#pragma unroll
    for (int r = 0; r < R3ROWS; ++r) {
        float lpA[3], lpB[3];
#pragma unroll
        for (int ch = 0; ch < 3; ch++) {
            const ulonglong2* g = (const ulonglong2*)&sg2[(r * 3 + ch) * 12];
            ulonglong2 g0 = g[0];
            u64 zr = g0.x, zi = g0.y;          // k = 0 term (E^0 = 1)
#pragma unroll
            for (int k = 1; k <= 5; ++k) {
                ulonglong2 gk = g[k];          // LDS.128: (re, im) broadcast pair
                zr = fma2_(gk.x, Ec[k], fma2_(neg2_(gk.y), Es[k], zr));
                zi = fma2_(gk.x, Es[k], fma2_(gk.y,        Ec[k], zi));
            }
            u64 m2 = fma2_(zr, zr, mul2_(zi, zi));
            float2 m = upk(m2);
            float m0 = fmaxf(m.x, 1e-30f), m1 = fmaxf(m.y, 1e-30f);
            lpA[ch] = m0 * __frsqrt_rn(m0);
            lpB[ch] = m1 * __frsqrt_rn(m1);
        }

        // hidden layer once per pixel (channel-independent)
        float hA[8], hB[8];
#pragma unroll
        for (int j = 0; j < 8; j++) {
            float aA = B1r[j], aB = B1r[j];
            aA = fmaf(W1r[j][0], lpA[0], aA);  aB = fmaf(W1r[j][0], lpB[0], aB);
            aA = fmaf(W1r[j][1], lpA[1], aA);  aB = fmaf(W1r[j][1], lpB[1], aB);
            aA = fmaf(W1r[j][2], lpA[2], aA);  aB = fmaf(W1r[j][2], lpB[2], aB);
            hA[j] = fmaxf(aA, 0.f);            hB[j] = fmaxf(aB, 0.f);
        }

#pragma unroll
        for (int ch = 0; ch < 3; ch++) {
            float yA = B2r[ch] + lpA[ch];
            float yB = B2r[ch] + lpB[ch];
#pragma unroll
            for (int j = 0; j < 8; j++) {
                yA = fmaf(W2r[ch][j], hA[j], yA);
                yB = fmaf(W2r[ch][j], hB[j], yB);
            }
            float2 yv;
            yv.x = __saturatef(yA);
            yv.y = __saturatef(yB);
            float2* orow = (float2*)(out + (((size_t)(b * 3 + ch) * HH) + (h0 + r)) * WW);
            orow[t] = yv;
        }
    }
}

// ---------------------------------------------------------------------------
extern "C" void kernel_launch(void* const* d_in, const int* in_sizes, int n_in,
                              void* d_out, int out_size) {
    const float* x  = (const float*)d_in[0];
    const float* w1 = (const float*)d_in[1];
    const float* b1 = (const float*)d_in[2];
    const float* w2 = (const float*)d_in[3];
    const float* b2 = (const float*)d_in[4];
    float* out = (float*)d_out;

    k1_coldft<<<dim3(NCHUNK, BB * CCH), 128>>>(x);
    k2_reduce<<<BB * CCH, 512>>>();
    k3_final<<<dim3(HH / R3ROWS, BB), 256>>>(w1, b1, w2, b2, out);
}